// round 13
// baseline (speedup 1.0000x reference)
#include <cuda_runtime.h>
#include <cuda_bf16.h>
#include <cstdint>
#include <math.h>

// ---------------------------------------------------------------------------
// Problem constants
// ---------------------------------------------------------------------------
#define BATCH   8
#define NTOK    4096
#define MTOT    32768          // BATCH*NTOK
#define MT_TILES 256           // MTOT/128
#define KCHUNKS 24             // logical K' = 1536 = 24 * 64 ([Ah|Al|Ah]x[Bh|Bh|Bl])
#define ATT_SCALE 0.125f
#define GEMM_GRID 296          // persistent CTAs: 2 per SM x 148 SMs

// ---------------------------------------------------------------------------
// Device scratch. Physical storage holds only UNIQUE chunks:
//   A: 16 chunks (0-7 = Ah, 8-15 = Al); logical kc>=16 re-reads Ah (kc-16).
//   B: 16 chunks (0-7 = Bh, 8-15 = Bl); logical kc in [8,16) re-reads Bh (kc-8),
//      logical kc>=16 reads Bl (kc-8).
// Tile (kc, t): 16KB SW128-swizzled 128x128B block at uint4 idx (kc*NT+t)*1024.
// ---------------------------------------------------------------------------
__device__ float g_qkv[(size_t)MTOT * 1536];                 // fp32 qkv
__device__ uint4 g_a1[(size_t)MTOT * 1024 * 2 / 16];         // x split
__device__ uint4 g_a2[(size_t)MTOT * 1024 * 2 / 16];         // attn out split
__device__ uint4 g_b1[(size_t)1536 * 1024 * 2 / 16];         // w_qkv split
__device__ uint4 g_b2[(size_t)512  * 1024 * 2 / 16];         // w_out split

// ---------------------------------------------------------------------------
// PTX helpers (sm_100 baseline-safe: no tcgen05)
// ---------------------------------------------------------------------------
__device__ __forceinline__ uint32_t smem_u32(const void* p) {
    uint32_t a;
    asm("{ .reg .u64 t; cvta.to.shared.u64 t, %1; cvt.u32.u64 %0, t; }"
        : "=r"(a) : "l"(p));
    return a;
}
__device__ __forceinline__ void mbar_init(uint32_t a, uint32_t n) {
    asm volatile("mbarrier.init.shared.b64 [%0], %1;" :: "r"(a), "r"(n) : "memory");
}
__device__ __forceinline__ void mbar_expect_tx(uint32_t a, uint32_t tx) {
    asm volatile("mbarrier.arrive.expect_tx.shared.b64 _, [%0], %1;"
                 :: "r"(a), "r"(tx) : "memory");
}
__device__ __forceinline__ void mbar_arrive(uint32_t a) {
    asm volatile("mbarrier.arrive.shared.b64 _, [%0];" :: "r"(a) : "memory");
}
__device__ __forceinline__ void mbar_wait(uint32_t a, uint32_t ph) {
    uint32_t done;
    asm volatile("{ .reg .pred p; mbarrier.try_wait.parity.acquire.cta.shared::cta.b64 p, [%1], %2; selp.b32 %0, 1, 0, p; }"
                 : "=r"(done) : "r"(a), "r"(ph) : "memory");
    while (!done) {
        asm volatile("{ .reg .pred p; mbarrier.try_wait.parity.acquire.cta.shared::cta.b64 p, [%1], %2, 0x989680; selp.b32 %0, 1, 0, p; }"
                     : "=r"(done) : "r"(a), "r"(ph) : "memory");
    }
}
__device__ __forceinline__ void bulk_g2s(uint32_t dst, const void* src,
                                         uint32_t bytes, uint32_t mbar) {
    asm volatile("cp.async.bulk.shared::cluster.global.mbarrier::complete_tx::bytes [%0], [%1], %2, [%3];"
                 :: "r"(dst), "l"(src), "r"(bytes), "r"(mbar) : "memory");
}
#define FENCE_ASYNC_SHARED() asm volatile("fence.proxy.async.shared::cta;" ::: "memory")

__device__ __forceinline__ void ldmat_x4(uint32_t& r0, uint32_t& r1,
                                         uint32_t& r2, uint32_t& r3, uint32_t addr) {
    asm volatile("ldmatrix.sync.aligned.m8n8.x4.shared.b16 {%0,%1,%2,%3}, [%4];"
                 : "=r"(r0), "=r"(r1), "=r"(r2), "=r"(r3) : "r"(addr));
}
__device__ __forceinline__ void mma_bf16(float& d0, float& d1, float& d2, float& d3,
                                         uint32_t a0, uint32_t a1, uint32_t a2, uint32_t a3,
                                         uint32_t b0, uint32_t b1) {
    asm volatile("mma.sync.aligned.m16n8k16.row.col.f32.bf16.bf16.f32 "
                 "{%0,%1,%2,%3}, {%4,%5,%6,%7}, {%8,%9}, {%0,%1,%2,%3};"
                 : "+f"(d0), "+f"(d1), "+f"(d2), "+f"(d3)
                 : "r"(a0), "r"(a1), "r"(a2), "r"(a3), "r"(b0), "r"(b1));
}

// ---------------------------------------------------------------------------
// bf16 split helpers
// ---------------------------------------------------------------------------
__device__ __forceinline__ uint32_t pack2(__nv_bfloat16 a, __nv_bfloat16 b) {
    return (uint32_t)__bfloat16_as_ushort(a) | ((uint32_t)__bfloat16_as_ushort(b) << 16);
}
__device__ __forceinline__ void split2(float a, float b, uint32_t& hi, uint32_t& lo) {
    __nv_bfloat16 ha = __float2bfloat16_rn(a), hb = __float2bfloat16_rn(b);
    __nv_bfloat16 la = __float2bfloat16_rn(a - __bfloat162float(ha));
    __nv_bfloat16 lb = __float2bfloat16_rn(b - __bfloat162float(hb));
    hi = pack2(ha, hb); lo = pack2(la, lb);
}
__device__ __forceinline__ uint32_t swz(uint32_t off) {   // SW128 swizzle
    return off ^ ((off >> 3) & 0x70);
}

// Logical chunk -> physical chunk index
__device__ __forceinline__ int a_src(int kc) { return (kc < 16) ? kc : kc - 16; }
__device__ __forceinline__ int b_src(int kc) { return (kc < 8) ? kc : kc - 8; }

// ---------------------------------------------------------------------------
// Conversion: x [32768,512] fp32 -> g_a1 unique chunks (Ah: 0-7, Al: 8-15)
// ---------------------------------------------------------------------------
__global__ __launch_bounds__(256) void conv_x_kernel(const float* __restrict__ x)
{
    const int t = blockIdx.x * 256 + threadIdx.x;      // < 32768*64
    const int m = t >> 6, c8 = t & 63;
    const int k = c8 << 3;

    const float* xr = x + (size_t)m * 512 + k;
    float4 v0 = *(const float4*)xr, v1 = *(const float4*)(xr + 4);
    uint32_t h[4], l[4];
    split2(v0.x, v0.y, h[0], l[0]); split2(v0.z, v0.w, h[1], l[1]);
    split2(v1.x, v1.y, h[2], l[2]); split2(v1.z, v1.w, h[3], l[3]);

    const int mt = m >> 7, r = m & 127;
    const int kc = k >> 6, c = k & 63;
    const uint32_t u4 = swz((uint32_t)(r * 128 + c * 2)) >> 4;

    g_a1[((size_t)(kc * MT_TILES + mt) << 10) + u4]       = make_uint4(h[0], h[1], h[2], h[3]);
    g_a1[((size_t)((8 + kc) * MT_TILES + mt) << 10) + u4] = make_uint4(l[0], l[1], l[2], l[3]);
}

// ---------------------------------------------------------------------------
// Conversion: weights [NROWS,512] fp32 -> unique chunks (Bh: 0-7, Bl: 8-15)
// ---------------------------------------------------------------------------
template <int WHICH>   // 1: w_qkv (NT=12), 2: w_out (NT=4)
__global__ __launch_bounds__(256) void conv_w_kernel(const float* __restrict__ w)
{
    constexpr int NT = (WHICH == 1) ? 12 : 4;
    const int t = blockIdx.x * 256 + threadIdx.x;      // < NT*128*64
    const int n = t >> 6, c8 = t & 63;
    const int k = c8 << 3;

    const float* wr = w + (size_t)n * 512 + k;
    float4 v0 = *(const float4*)wr, v1 = *(const float4*)(wr + 4);
    uint32_t h[4], l[4];
    split2(v0.x, v0.y, h[0], l[0]); split2(v0.z, v0.w, h[1], l[1]);
    split2(v1.x, v1.y, h[2], l[2]); split2(v1.z, v1.w, h[3], l[3]);

    const int nt = n >> 7, r = n & 127;
    const int kc = k >> 6, c = k & 63;
    const uint32_t u4 = swz((uint32_t)(r * 128 + c * 2)) >> 4;

    uint4* dst = (WHICH == 1) ? g_b1 : g_b2;
    dst[((size_t)(kc * NT + nt) << 10) + u4]       = make_uint4(h[0], h[1], h[2], h[3]);
    dst[((size_t)((8 + kc) * NT + nt) << 10) + u4] = make_uint4(l[0], l[1], l[2], l[3]);
}

// ---------------------------------------------------------------------------
// PERSISTENT mma.sync bf16 GEMM: C = Ah*Bh + Al*Bh + Ah*Bl, 24 chunks/tile.
// Grid = 296 CTAs (2/SM); each CTA loops tiles tile = bid + 296*i.
// The chunk pipeline (stage = c%3, parity = (c/3)&1) runs CONTINUOUSLY across
// tile boundaries (24%3==0 keeps the recurrence identical to the validated
// per-tile version): producers prefetch into the next tile while the current
// tile's epilogue runs, so the TMA pipeline never drains. Prologue/mbar-init
// paid once per CTA; wave tail shrinks to <= 1 tile-time.
// Consumer release = __syncwarp + fence.proxy.async + arrive (R6 race fix).
// ---------------------------------------------------------------------------
#define SMEM_GEMM_BYTES (1024 + 1024 + 3 * 32768)

template <int WHICH>   // 1: qkv GEMM (C=g_qkv, NT=12), 2: out GEMM (C=out+bias, NT=4)
__global__ __launch_bounds__(256, 2) void gemm_kernel(float* __restrict__ CoutP,
                                                      const float* __restrict__ bias)
{
    constexpr int NT = (WHICH == 1) ? 12 : 4;
    constexpr int NCOLS = NT * 128;
    constexpr int NTILES = NT * MT_TILES;
    extern __shared__ __align__(1024) char smem_raw[];
    const uint32_t sb = (smem_u32(smem_raw) + 1023u) & ~1023u;

    const int tid  = threadIdx.x;
    const int wid  = tid >> 5, l = tid & 31;
    const int bid  = blockIdx.x;
    const int m0   = (wid >> 2) * 64;      // warp m offset in tile
    const int n0   = (wid & 3)  * 32;      // warp n offset in tile
    const uint32_t xmask = (uint32_t)(l & 7) << 4;

    const char* Abase = (WHICH == 1) ? (const char*)g_a1 : (const char*)g_a2;
    const char* Bbase = (WHICH == 1) ? (const char*)g_b1 : (const char*)g_b2;
    float* C = (WHICH == 1) ? g_qkv : CoutP;

    // smem: sb+0..23: full mbars (3x8B); sb+32..55: empty mbars (3x8B);
    //       buffers at sb+1024, (A 16KB | B 16KB) per stage.
    if (tid == 0) {
        #pragma unroll
        for (int s = 0; s < 3; s++) {
            mbar_init(sb + 8 * s, 1);            // full: 1 producer arrive (expect_tx)
            mbar_init(sb + 32 + 8 * s, 8);       // empty: 8 warp arrivals
        }
        FENCE_ASYNC_SHARED();
    }
    __syncthreads();

    // Prologue: stage chunks kc=0..2 of this CTA's first tile.
    if (tid == 0) {
        const int nt0 = bid % NT, mt0 = bid / NT;
        #pragma unroll
        for (int s = 0; s < 3; s++) {
            mbar_expect_tx(sb + 8 * s, 32768);
            bulk_g2s(sb + 1024 + s * 32768,
                     Abase + ((size_t)(a_src(s) * MT_TILES + mt0)) * 16384, 16384, sb + 8 * s);
            bulk_g2s(sb + 1024 + s * 32768 + 16384,
                     Bbase + ((size_t)(b_src(s) * NT + nt0)) * 16384, 16384, sb + 8 * s);
        }
    }

    float acc[4][4][4];
    #pragma unroll
    for (int i = 0; i < 4; i++)
        #pragma unroll
        for (int j = 0; j < 4; j++)
            #pragma unroll
            for (int q = 0; q < 4; q++) acc[i][j][q] = 0.f;

    // Per-lane address components (constant across chunks/tiles)
    const uint32_t arow = (uint32_t)(m0 + (l & 15)) * 128;               // A row bytes
    const uint32_t brow = (uint32_t)(n0 + 8 * ((l >> 4) & 1) + (l & 7)) * 128;
    const uint32_t acol_l = 16u * (uint32_t)(l >> 4);                    // A k-byte sel
    const uint32_t bcol_l = 16u * (uint32_t)((l >> 3) & 1);              // B k-byte sel

    int tile = bid;
    int kc = 0, s = 0;
    uint32_t ph = 0;

    #pragma unroll 1
    while (true) {
        mbar_wait(sb + 8 * s, ph);               // chunk data ready

        const uint32_t abuf = sb + 1024 + s * 32768;
        const uint32_t bbuf = abuf + 16384;

        #pragma unroll
        for (int ks = 0; ks < 4; ks++) {
            uint32_t a[4][4];
            #pragma unroll
            for (int mi = 0; mi < 4; mi++) {
                const uint32_t addr = abuf + arow + (uint32_t)(mi * 16 * 128)
                                    + ((32u * ks + acol_l) ^ xmask);
                ldmat_x4(a[mi][0], a[mi][1], a[mi][2], a[mi][3], addr);
            }
            uint32_t bfr[2][4];
            #pragma unroll
            for (int jj = 0; jj < 2; jj++) {
                const uint32_t addr = bbuf + brow + (uint32_t)(jj * 16 * 128)
                                    + ((32u * ks + bcol_l) ^ xmask);
                ldmat_x4(bfr[jj][0], bfr[jj][1], bfr[jj][2], bfr[jj][3], addr);
            }
            #pragma unroll
            for (int mi = 0; mi < 4; mi++)
                #pragma unroll
                for (int nj = 0; nj < 4; nj++)
                    mma_bf16(acc[mi][nj][0], acc[mi][nj][1], acc[mi][nj][2], acc[mi][nj][3],
                             a[mi][0], a[mi][1], a[mi][2], a[mi][3],
                             bfr[nj >> 1][(nj & 1) * 2], bfr[nj >> 1][(nj & 1) * 2 + 1]);
        }

        // Consumer release: converge lanes, then make this warp's generic-proxy
        // smem reads visible to the async proxy BEFORE signaling stage empty.
        __syncwarp();
        FENCE_ASYNC_SHARED();
        if (l == 0) mbar_arrive(sb + 32 + 8 * s);

        // Refill stage s with chunk kc+3 (possibly in the NEXT tile).
        {
            int kc3 = kc + 3, tile3 = tile;
            if (kc3 >= KCHUNKS) { kc3 -= KCHUNKS; tile3 += GEMM_GRID; }
            if (tile3 < NTILES && wid == (kc3 & 7) && l == 0) {
                const int nt3 = tile3 % NT, mt3 = tile3 / NT;
                mbar_wait(sb + 32 + 8 * s, ph);      // all warps released stage s
                mbar_expect_tx(sb + 8 * s, 32768);
                bulk_g2s(abuf, Abase + ((size_t)(a_src(kc3) * MT_TILES + mt3)) * 16384,
                         16384, sb + 8 * s);
                bulk_g2s(bbuf, Bbase + ((size_t)(b_src(kc3) * NT + nt3)) * 16384,
                         16384, sb + 8 * s);
            }
        }

        // Advance pipeline phase.
        if (++s == 3) { s = 0; ph ^= 1; }

        // Tile boundary: epilogue + acc reset, then next tile (pipeline stays hot).
        if (++kc == KCHUNKS) {
            const int nt = tile % NT, mt = tile / NT;
            float2 bv[4];
            if (WHICH == 2) {
                #pragma unroll
                for (int nj = 0; nj < 4; nj++) {
                    const int col = nt * 128 + n0 + 8 * nj + 2 * (l & 3);
                    bv[nj] = make_float2(__ldg(&bias[col]), __ldg(&bias[col + 1]));
                }
            }
            #pragma unroll
            for (int mi = 0; mi < 4; mi++) {
                #pragma unroll
                for (int half = 0; half < 2; half++) {
                    const int row = mt * 128 + m0 + 16 * mi + (l >> 2) + 8 * half;
                    float* cr = C + (size_t)row * NCOLS + nt * 128;
                    #pragma unroll
                    for (int nj = 0; nj < 4; nj++) {
                        const int col = n0 + 8 * nj + 2 * (l & 3);
                        float v0 = acc[mi][nj][2 * half];
                        float v1 = acc[mi][nj][2 * half + 1];
                        if (WHICH == 2) { v0 += bv[nj].x; v1 += bv[nj].y; }
                        *(float2*)&cr[col] = make_float2(v0, v1);
                    }
                }
            }
            #pragma unroll
            for (int i = 0; i < 4; i++)
                #pragma unroll
                for (int j = 0; j < 4; j++)
                    #pragma unroll
                    for (int q = 0; q < 4; q++) acc[i][j][q] = 0.f;

            kc = 0;
            tile += GEMM_GRID;
            if (tile >= NTILES) break;
        }
    }
}

// ---------------------------------------------------------------------------
// Block-diagonal attention, two heads per block. One block (256 threads) per
// (b, head-pair, bi, bj): 16 tokens, heads 2*hp and 2*hp+1. Each row load is
// 512B contiguous. Writes output directly in split/chunked/swizzled bf16
// layout g_a2 (hi chunk h, lo chunk 8+h).
// ---------------------------------------------------------------------------
__global__ __launch_bounds__(256) void attn_kernel()
{
    __shared__ float qs[16][132], ks[16][132], vs[16][132];
    __shared__ float ps[2][16][17];

    const int gid = blockIdx.x;            // 0..8191
    const int bj = gid & 127;
    const int bi = (gid >> 7) & 1;
    const int hp = (gid >> 8) & 3;         // head pair
    const int b  = gid >> 10;

    const int tid = threadIdx.x;

    // token index for group row r (r = x*4+y): n = (bi*4+x)*512 + bj*4+y
    #pragma unroll
    for (int t = tid; t < 512; t += 256) {
        const int r = t >> 5, c = (t & 31) * 4;
        const int x = r >> 2, y = r & 3;
        const int n = (bi * 4 + x) * 512 + bj * 4 + y;
        const size_t base = ((size_t)(b * NTOK + n)) * 1536 + hp * 128 + c;
        *(float4*)&qs[r][c] = *(const float4*)(g_qkv + base);
        *(float4*)&ks[r][c] = *(const float4*)(g_qkv + base + 512);
        *(float4*)&vs[r][c] = *(const float4*)(g_qkv + base + 1024);
    }
    __syncthreads();

    // 512 dots (2 heads x 16 x 16), each thread computes 2.
    #pragma unroll
    for (int t = tid; t < 512; t += 256) {
        const int hh = t >> 8, i = (t >> 4) & 15, j = t & 15;
        const int db = hh * 64;
        float s = 0.f;
        #pragma unroll
        for (int d = 0; d < 64; d++) s = fmaf(qs[i][db + d], ks[j][db + d], s);
        ps[hh][i][j] = s * ATT_SCALE;
    }
    __syncthreads();

    // Row softmax: 32 threads (2 heads x 16 rows)
    if (tid < 32) {
        const int hh = tid >> 4, i = tid & 15;
        float mx = ps[hh][i][0];
        #pragma unroll
        for (int j = 1; j < 16; j++) mx = fmaxf(mx, ps[hh][i][j]);
        float sum = 0.f;
        #pragma unroll
        for (int j = 0; j < 16; j++) {
            const float e = __expf(ps[hh][i][j] - mx);
            ps[hh][i][j] = e;
            sum += e;
        }
        const float inv = 1.f / sum;
        #pragma unroll
        for (int j = 0; j < 16; j++) ps[hh][i][j] *= inv;
    }
    __syncthreads();

    // out[i][hh*64 + d]: thread owns (row r, head hh, 8 contiguous d)
    const int r  = tid >> 4;
    const int cc = tid & 15;
    const int hh = cc >> 3;
    const int d0 = (cc & 7) * 8;

    float o[8];
    #pragma unroll
    for (int dd = 0; dd < 8; dd++) o[dd] = 0.f;
    #pragma unroll
    for (int j = 0; j < 16; j++) {
        const float pv = ps[hh][r][j];
        #pragma unroll
        for (int dd = 0; dd < 8; dd++)
            o[dd] = fmaf(pv, vs[j][hh * 64 + d0 + dd], o[dd]);
    }

    uint32_t hhv[4], llv[4];
    split2(o[0], o[1], hhv[0], llv[0]); split2(o[2], o[3], hhv[1], llv[1]);
    split2(o[4], o[5], hhv[2], llv[2]); split2(o[6], o[7], hhv[3], llv[3]);

    const int x = r >> 2, y = r & 3;
    const int n = (bi * 4 + x) * 512 + bj * 4 + y;
    const int m = b * NTOK + n;
    const int mt = m >> 7, rr = m & 127;
    const int h = hp * 2 + hh;
    const uint32_t u4 = swz((uint32_t)(rr * 128 + d0 * 2)) >> 4;

    g_a2[((size_t)(h * MT_TILES + mt) << 10) + u4]       = make_uint4(hhv[0], hhv[1], hhv[2], hhv[3]);
    g_a2[((size_t)((8 + h) * MT_TILES + mt) << 10) + u4] = make_uint4(llv[0], llv[1], llv[2], llv[3]);
}

// ---------------------------------------------------------------------------
extern "C" void kernel_launch(void* const* d_in, const int* in_sizes, int n_in,
                              void* d_out, int out_size)
{
    const float* x     = (const float*)d_in[0];   // [8,4096,512]
    const float* w_qkv = (const float*)d_in[1];   // [1536,512]
    const float* w_out = (const float*)d_in[2];   // [512,512]
    const float* b_out = (const float*)d_in[3];   // [512]
    float* out = (float*)d_out;                   // [8,4096,512]

    cudaFuncSetAttribute(gemm_kernel<1>, cudaFuncAttributeMaxDynamicSharedMemorySize, SMEM_GEMM_BYTES);
    cudaFuncSetAttribute(gemm_kernel<2>, cudaFuncAttributeMaxDynamicSharedMemorySize, SMEM_GEMM_BYTES);

    // 1) split/convert inputs into chunked bf16 layouts (unique chunks only)
    conv_x_kernel<<<(MTOT * 64) / 256, 256>>>(x);
    conv_w_kernel<1><<<(1536 * 64) / 256, 256>>>(w_qkv);
    conv_w_kernel<2><<<(512 * 64) / 256, 256>>>(w_out);

    // 2) QKV GEMM (persistent, tensor cores): -> g_qkv fp32 [32768,1536]
    gemm_kernel<1><<<GEMM_GRID, 256, SMEM_GEMM_BYTES>>>(nullptr, nullptr);

    // 3) block-diagonal attention (2 heads/block) -> g_a2 (split bf16)
    attn_kernel<<<BATCH * 4 * 2 * 128, 256>>>();

    // 4) output GEMM + bias (persistent): -> out fp32 [32768,512]
    gemm_kernel<2><<<GEMM_GRID, 256, SMEM_GEMM_BYTES>>>(out, b_out);
}

// round 14
// speedup vs baseline: 1.1081x; 1.1081x over previous
#include <cuda_runtime.h>
#include <cuda_bf16.h>
#include <cstdint>
#include <math.h>

// ---------------------------------------------------------------------------
// Problem constants
// ---------------------------------------------------------------------------
#define BATCH   8
#define NTOK    4096
#define MTOT    32768          // BATCH*NTOK
#define MT_TILES 256           // MTOT/128
#define KCHUNKS 24             // logical K' = 1536 = 24 * 64 ([Ah|Al|Ah]x[Bh|Bh|Bl])
#define ATT_SCALE 0.125f

// ---------------------------------------------------------------------------
// Device scratch. Physical storage holds only UNIQUE chunks:
//   A: 16 chunks (0-7 = Ah, 8-15 = Al); logical kc>=16 re-reads Ah (kc-16).
//   B: 16 chunks (0-7 = Bh, 8-15 = Bl); logical kc in [8,16) re-reads Bh (kc-8),
//      logical kc>=16 reads Bl (kc-8).
// Tile (kc, t): 16KB SW128-swizzled 128x128B block at uint4 idx (kc*NT+t)*1024.
// ---------------------------------------------------------------------------
__device__ float g_qkv[(size_t)MTOT * 1536];                 // fp32 qkv
__device__ uint4 g_a1[(size_t)MTOT * 1024 * 2 / 16];         // x split
__device__ uint4 g_a2[(size_t)MTOT * 1024 * 2 / 16];         // attn out split
__device__ uint4 g_b1[(size_t)1536 * 1024 * 2 / 16];         // w_qkv split
__device__ uint4 g_b2[(size_t)512  * 1024 * 2 / 16];         // w_out split

// ---------------------------------------------------------------------------
// PTX helpers (sm_100 baseline-safe: no tcgen05)
// ---------------------------------------------------------------------------
__device__ __forceinline__ uint32_t smem_u32(const void* p) {
    uint32_t a;
    asm("{ .reg .u64 t; cvta.to.shared.u64 t, %1; cvt.u32.u64 %0, t; }"
        : "=r"(a) : "l"(p));
    return a;
}
__device__ __forceinline__ void mbar_init(uint32_t a, uint32_t n) {
    asm volatile("mbarrier.init.shared.b64 [%0], %1;" :: "r"(a), "r"(n) : "memory");
}
__device__ __forceinline__ void mbar_expect_tx(uint32_t a, uint32_t tx) {
    asm volatile("mbarrier.arrive.expect_tx.shared.b64 _, [%0], %1;"
                 :: "r"(a), "r"(tx) : "memory");
}
__device__ __forceinline__ void mbar_arrive(uint32_t a) {
    asm volatile("mbarrier.arrive.shared.b64 _, [%0];" :: "r"(a) : "memory");
}
__device__ __forceinline__ void mbar_wait(uint32_t a, uint32_t ph) {
    uint32_t done;
    asm volatile("{ .reg .pred p; mbarrier.try_wait.parity.acquire.cta.shared::cta.b64 p, [%1], %2; selp.b32 %0, 1, 0, p; }"
                 : "=r"(done) : "r"(a), "r"(ph) : "memory");
    while (!done) {
        asm volatile("{ .reg .pred p; mbarrier.try_wait.parity.acquire.cta.shared::cta.b64 p, [%1], %2, 0x989680; selp.b32 %0, 1, 0, p; }"
                     : "=r"(done) : "r"(a), "r"(ph) : "memory");
    }
}
__device__ __forceinline__ void bulk_g2s(uint32_t dst, const void* src,
                                         uint32_t bytes, uint32_t mbar) {
    asm volatile("cp.async.bulk.shared::cluster.global.mbarrier::complete_tx::bytes [%0], [%1], %2, [%3];"
                 :: "r"(dst), "l"(src), "r"(bytes), "r"(mbar) : "memory");
}
#define FENCE_ASYNC_SHARED() asm volatile("fence.proxy.async.shared::cta;" ::: "memory")

__device__ __forceinline__ void ldmat_x4(uint32_t& r0, uint32_t& r1,
                                         uint32_t& r2, uint32_t& r3, uint32_t addr) {
    asm volatile("ldmatrix.sync.aligned.m8n8.x4.shared.b16 {%0,%1,%2,%3}, [%4];"
                 : "=r"(r0), "=r"(r1), "=r"(r2), "=r"(r3) : "r"(addr));
}
__device__ __forceinline__ void mma_bf16(float& d0, float& d1, float& d2, float& d3,
                                         uint32_t a0, uint32_t a1, uint32_t a2, uint32_t a3,
                                         uint32_t b0, uint32_t b1) {
    asm volatile("mma.sync.aligned.m16n8k16.row.col.f32.bf16.bf16.f32 "
                 "{%0,%1,%2,%3}, {%4,%5,%6,%7}, {%8,%9}, {%0,%1,%2,%3};"
                 : "+f"(d0), "+f"(d1), "+f"(d2), "+f"(d3)
                 : "r"(a0), "r"(a1), "r"(a2), "r"(a3), "r"(b0), "r"(b1));
}

// ---------------------------------------------------------------------------
// bf16 split helpers
// ---------------------------------------------------------------------------
__device__ __forceinline__ uint32_t pack2(__nv_bfloat16 a, __nv_bfloat16 b) {
    return (uint32_t)__bfloat16_as_ushort(a) | ((uint32_t)__bfloat16_as_ushort(b) << 16);
}
__device__ __forceinline__ void split2(float a, float b, uint32_t& hi, uint32_t& lo) {
    __nv_bfloat16 ha = __float2bfloat16_rn(a), hb = __float2bfloat16_rn(b);
    __nv_bfloat16 la = __float2bfloat16_rn(a - __bfloat162float(ha));
    __nv_bfloat16 lb = __float2bfloat16_rn(b - __bfloat162float(hb));
    hi = pack2(ha, hb); lo = pack2(la, lb);
}
__device__ __forceinline__ uint32_t swz(uint32_t off) {   // SW128 swizzle
    return off ^ ((off >> 3) & 0x70);
}

// Logical chunk -> physical chunk index
__device__ __forceinline__ int a_src(int kc) { return (kc < 16) ? kc : kc - 16; }
__device__ __forceinline__ int b_src(int kc) { return (kc < 8) ? kc : kc - 8; }

// ---------------------------------------------------------------------------
// FUSED conversion kernel: one launch converts x, w_qkv, w_out into their
// chunked/swizzled bf16 hi/lo layouts. Grid partition by blockIdx.x:
//   [0, 8192)          -> x      (32768 rows, MT_TILES=256 row-tiles)
//   [8192, 8192+384)   -> w_qkv  (1536 rows, NT=12)
//   [8576, 8576+128)   -> w_out  (512 rows,  NT=4)
// Each thread handles one (row, 8-col group) of a [rows, 512] fp32 matrix.
// ---------------------------------------------------------------------------
#define CONV_XB    8192
#define CONV_W1B   384
#define CONV_GRID  (CONV_XB + CONV_W1B + 128)

__global__ __launch_bounds__(256) void conv_all_kernel(
    const float* __restrict__ x, const float* __restrict__ w_qkv,
    const float* __restrict__ w_out)
{
    int blk = blockIdx.x;
    const float* src;
    uint4* dst;
    int tilesN;                 // tiles along the row dimension
    if (blk < CONV_XB)                { src = x;     dst = g_a1; tilesN = MT_TILES; }
    else if (blk < CONV_XB + CONV_W1B){ src = w_qkv; dst = g_b1; tilesN = 12; blk -= CONV_XB; }
    else                              { src = w_out; dst = g_b2; tilesN = 4;  blk -= CONV_XB + CONV_W1B; }

    const int t = blk * 256 + threadIdx.x;
    const int row = t >> 6, c8 = t & 63;
    const int k = c8 << 3;

    const float* rr = src + (size_t)row * 512 + k;
    float4 v0 = *(const float4*)rr, v1 = *(const float4*)(rr + 4);
    uint32_t h[4], l[4];
    split2(v0.x, v0.y, h[0], l[0]); split2(v0.z, v0.w, h[1], l[1]);
    split2(v1.x, v1.y, h[2], l[2]); split2(v1.z, v1.w, h[3], l[3]);

    const int rt = row >> 7, r = row & 127;
    const int kc = k >> 6, c = k & 63;
    const uint32_t u4 = swz((uint32_t)(r * 128 + c * 2)) >> 4;

    dst[((size_t)(kc * tilesN + rt) << 10) + u4]       = make_uint4(h[0], h[1], h[2], h[3]);
    dst[((size_t)((8 + kc) * tilesN + rt) << 10) + u4] = make_uint4(l[0], l[1], l[2], l[3]);
}

// ---------------------------------------------------------------------------
// mma.sync bf16 GEMM: C = Ah*Bh + Al*Bh + Ah*Bl over 24 logical chunks of 64.
// 128x128 CTA tile, 256 threads (8 warps, 2x4 grid, 64x32 warp tile),
// 3-stage cp.async.bulk pipeline with per-warp empty barriers.
// Consumer release = __syncwarp + fence.proxy.async + arrive.
// Rotating producer (warp (kc+3)&7). [Exact R11 configuration — best known.]
// ---------------------------------------------------------------------------
#define SMEM_GEMM_BYTES (1024 + 1024 + 3 * 32768)

template <int WHICH>   // 1: qkv GEMM (C=g_qkv, NT=12), 2: out GEMM (C=out+bias, NT=4)
__global__ __launch_bounds__(256, 2) void gemm_kernel(float* __restrict__ CoutP,
                                                      const float* __restrict__ bias)
{
    constexpr int NT = (WHICH == 1) ? 12 : 4;
    constexpr int NCOLS = NT * 128;
    extern __shared__ __align__(1024) char smem_raw[];
    const uint32_t sb = (smem_u32(smem_raw) + 1023u) & ~1023u;

    const int tid  = threadIdx.x;
    const int wid  = tid >> 5, l = tid & 31;
    const int mt   = blockIdx.y, nt = blockIdx.x;
    const int m0   = (wid >> 2) * 64;      // warp m offset in tile
    const int n0   = (wid & 3)  * 32;      // warp n offset in tile
    const uint32_t xmask = (uint32_t)(l & 7) << 4;

    const char* Abase = (WHICH == 1) ? (const char*)g_a1 : (const char*)g_a2;
    const char* Bbase = (WHICH == 1) ? (const char*)g_b1 : (const char*)g_b2;
    float* C = (WHICH == 1) ? g_qkv : CoutP;

    // smem: sb+0..23: full mbars (3x8B); sb+32..55: empty mbars (3x8B);
    //       buffers at sb+1024, (A 16KB | B 16KB) per stage.
    if (tid == 0) {
        #pragma unroll
        for (int s = 0; s < 3; s++) {
            mbar_init(sb + 8 * s, 1);            // full: 1 producer arrive (expect_tx)
            mbar_init(sb + 32 + 8 * s, 8);       // empty: 8 warp arrivals
        }
        FENCE_ASYNC_SHARED();
    }
    __syncthreads();

    if (tid == 0) {
        #pragma unroll
        for (int s = 0; s < 3; s++) {
            mbar_expect_tx(sb + 8 * s, 32768);
            bulk_g2s(sb + 1024 + s * 32768,
                     Abase + ((size_t)(a_src(s) * MT_TILES + mt)) * 16384, 16384, sb + 8 * s);
            bulk_g2s(sb + 1024 + s * 32768 + 16384,
                     Bbase + ((size_t)(b_src(s) * NT + nt)) * 16384, 16384, sb + 8 * s);
        }
    }

    float acc[4][4][4];
    #pragma unroll
    for (int i = 0; i < 4; i++)
        #pragma unroll
        for (int j = 0; j < 4; j++)
            #pragma unroll
            for (int q = 0; q < 4; q++) acc[i][j][q] = 0.f;

    // Per-lane address components (constant across chunks/steps)
    const uint32_t arow = (uint32_t)(m0 + (l & 15)) * 128;               // A row bytes
    const uint32_t brow = (uint32_t)(n0 + 8 * ((l >> 4) & 1) + (l & 7)) * 128;
    const uint32_t acol_l = 16u * (uint32_t)(l >> 4);                    // A k-byte sel
    const uint32_t bcol_l = 16u * (uint32_t)((l >> 3) & 1);              // B k-byte sel

    #pragma unroll 1
    for (int kc = 0; kc < KCHUNKS; kc++) {
        const int rnd = kc / 3;
        const int s = kc - rnd * 3;
        const uint32_t ph = (uint32_t)(rnd & 1);
        mbar_wait(sb + 8 * s, ph);               // chunk data ready

        const uint32_t abuf = sb + 1024 + s * 32768;
        const uint32_t bbuf = abuf + 16384;

        #pragma unroll
        for (int ks = 0; ks < 4; ks++) {
            uint32_t a[4][4];
            #pragma unroll
            for (int mi = 0; mi < 4; mi++) {
                const uint32_t addr = abuf + arow + (uint32_t)(mi * 16 * 128)
                                    + ((32u * ks + acol_l) ^ xmask);
                ldmat_x4(a[mi][0], a[mi][1], a[mi][2], a[mi][3], addr);
            }
            uint32_t bfr[2][4];
            #pragma unroll
            for (int jj = 0; jj < 2; jj++) {
                const uint32_t addr = bbuf + brow + (uint32_t)(jj * 16 * 128)
                                    + ((32u * ks + bcol_l) ^ xmask);
                ldmat_x4(bfr[jj][0], bfr[jj][1], bfr[jj][2], bfr[jj][3], addr);
            }
            #pragma unroll
            for (int mi = 0; mi < 4; mi++)
                #pragma unroll
                for (int nj = 0; nj < 4; nj++)
                    mma_bf16(acc[mi][nj][0], acc[mi][nj][1], acc[mi][nj][2], acc[mi][nj][3],
                             a[mi][0], a[mi][1], a[mi][2], a[mi][3],
                             bfr[nj >> 1][(nj & 1) * 2], bfr[nj >> 1][(nj & 1) * 2 + 1]);
        }

        // Consumer release: converge lanes, then make this warp's generic-proxy
        // smem reads visible to the async proxy BEFORE signaling stage empty.
        __syncwarp();
        FENCE_ASYNC_SHARED();
        if (l == 0) mbar_arrive(sb + 32 + 8 * s);

        // Rotating producer: warp (kc+3)&7, lane 0, refills stage s for chunk
        // kc+3 once all 8 warps have released it. Others run ahead freely.
        if (kc + 3 < KCHUNKS && wid == ((kc + 3) & 7) && l == 0) {
            mbar_wait(sb + 32 + 8 * s, ph);      // all consumed
            mbar_expect_tx(sb + 8 * s, 32768);
            bulk_g2s(abuf, Abase + ((size_t)(a_src(kc + 3) * MT_TILES + mt)) * 16384,
                     16384, sb + 8 * s);
            bulk_g2s(bbuf, Bbase + ((size_t)(b_src(kc + 3) * NT + nt)) * 16384,
                     16384, sb + 8 * s);
        }
    }

    // Epilogue: acc quad q: (d0,d1)->row l>>2, cols 2(l&3)+{0,1}; (d2,d3)->row+8
    float2 bv[4];
    if (WHICH == 2) {
        #pragma unroll
        for (int nj = 0; nj < 4; nj++) {
            const int col = nt * 128 + n0 + 8 * nj + 2 * (l & 3);
            bv[nj] = make_float2(__ldg(&bias[col]), __ldg(&bias[col + 1]));
        }
    }
    #pragma unroll
    for (int mi = 0; mi < 4; mi++) {
        #pragma unroll
        for (int half = 0; half < 2; half++) {
            const int row = mt * 128 + m0 + 16 * mi + (l >> 2) + 8 * half;
            float* cr = C + (size_t)row * NCOLS + nt * 128;
            #pragma unroll
            for (int nj = 0; nj < 4; nj++) {
                const int col = n0 + 8 * nj + 2 * (l & 3);
                float v0 = acc[mi][nj][2 * half];
                float v1 = acc[mi][nj][2 * half + 1];
                if (WHICH == 2) { v0 += bv[nj].x; v1 += bv[nj].y; }
                *(float2*)&cr[col] = make_float2(v0, v1);
            }
        }
    }
}

// ---------------------------------------------------------------------------
// Block-diagonal attention, two heads per block. One block (256 threads) per
// (b, head-pair, bi, bj): 16 tokens, heads 2*hp and 2*hp+1. Each row load is
// 512B contiguous. Writes output directly in split/chunked/swizzled bf16
// layout g_a2 (hi chunk h, lo chunk 8+h).
// ---------------------------------------------------------------------------
__global__ __launch_bounds__(256) void attn_kernel()
{
    __shared__ float qs[16][132], ks[16][132], vs[16][132];
    __shared__ float ps[2][16][17];

    const int gid = blockIdx.x;            // 0..8191
    const int bj = gid & 127;
    const int bi = (gid >> 7) & 1;
    const int hp = (gid >> 8) & 3;         // head pair
    const int b  = gid >> 10;

    const int tid = threadIdx.x;

    // token index for group row r (r = x*4+y): n = (bi*4+x)*512 + bj*4+y
    #pragma unroll
    for (int t = tid; t < 512; t += 256) {
        const int r = t >> 5, c = (t & 31) * 4;
        const int x = r >> 2, y = r & 3;
        const int n = (bi * 4 + x) * 512 + bj * 4 + y;
        const size_t base = ((size_t)(b * NTOK + n)) * 1536 + hp * 128 + c;
        *(float4*)&qs[r][c] = *(const float4*)(g_qkv + base);
        *(float4*)&ks[r][c] = *(const float4*)(g_qkv + base + 512);
        *(float4*)&vs[r][c] = *(const float4*)(g_qkv + base + 1024);
    }
    __syncthreads();

    // 512 dots (2 heads x 16 x 16), each thread computes 2.
    #pragma unroll
    for (int t = tid; t < 512; t += 256) {
        const int hh = t >> 8, i = (t >> 4) & 15, j = t & 15;
        const int db = hh * 64;
        float s = 0.f;
        #pragma unroll
        for (int d = 0; d < 64; d++) s = fmaf(qs[i][db + d], ks[j][db + d], s);
        ps[hh][i][j] = s * ATT_SCALE;
    }
    __syncthreads();

    // Row softmax: 32 threads (2 heads x 16 rows)
    if (tid < 32) {
        const int hh = tid >> 4, i = tid & 15;
        float mx = ps[hh][i][0];
        #pragma unroll
        for (int j = 1; j < 16; j++) mx = fmaxf(mx, ps[hh][i][j]);
        float sum = 0.f;
        #pragma unroll
        for (int j = 0; j < 16; j++) {
            const float e = __expf(ps[hh][i][j] - mx);
            ps[hh][i][j] = e;
            sum += e;
        }
        const float inv = 1.f / sum;
        #pragma unroll
        for (int j = 0; j < 16; j++) ps[hh][i][j] *= inv;
    }
    __syncthreads();

    // out[i][hh*64 + d]: thread owns (row r, head hh, 8 contiguous d)
    const int r  = tid >> 4;
    const int cc = tid & 15;
    const int hh = cc >> 3;
    const int d0 = (cc & 7) * 8;

    float o[8];
    #pragma unroll
    for (int dd = 0; dd < 8; dd++) o[dd] = 0.f;
    #pragma unroll
    for (int j = 0; j < 16; j++) {
        const float pv = ps[hh][r][j];
        #pragma unroll
        for (int dd = 0; dd < 8; dd++)
            o[dd] = fmaf(pv, vs[j][hh * 64 + d0 + dd], o[dd]);
    }

    uint32_t hhv[4], llv[4];
    split2(o[0], o[1], hhv[0], llv[0]); split2(o[2], o[3], hhv[1], llv[1]);
    split2(o[4], o[5], hhv[2], llv[2]); split2(o[6], o[7], hhv[3], llv[3]);

    const int x = r >> 2, y = r & 3;
    const int n = (bi * 4 + x) * 512 + bj * 4 + y;
    const int m = b * NTOK + n;
    const int mt = m >> 7, rr = m & 127;
    const int h = hp * 2 + hh;
    const uint32_t u4 = swz((uint32_t)(rr * 128 + d0 * 2)) >> 4;

    g_a2[((size_t)(h * MT_TILES + mt) << 10) + u4]       = make_uint4(hhv[0], hhv[1], hhv[2], hhv[3]);
    g_a2[((size_t)((8 + h) * MT_TILES + mt) << 10) + u4] = make_uint4(llv[0], llv[1], llv[2], llv[3]);
}

// ---------------------------------------------------------------------------
extern "C" void kernel_launch(void* const* d_in, const int* in_sizes, int n_in,
                              void* d_out, int out_size)
{
    const float* x     = (const float*)d_in[0];   // [8,4096,512]
    const float* w_qkv = (const float*)d_in[1];   // [1536,512]
    const float* w_out = (const float*)d_in[2];   // [512,512]
    const float* b_out = (const float*)d_in[3];   // [512]
    float* out = (float*)d_out;                   // [8,4096,512]

    cudaFuncSetAttribute(gemm_kernel<1>, cudaFuncAttributeMaxDynamicSharedMemorySize, SMEM_GEMM_BYTES);
    cudaFuncSetAttribute(gemm_kernel<2>, cudaFuncAttributeMaxDynamicSharedMemorySize, SMEM_GEMM_BYTES);

    // 1) fused split/convert of x, w_qkv, w_out (one launch)
    conv_all_kernel<<<CONV_GRID, 256>>>(x, w_qkv, w_out);

    // 2) QKV GEMM (tensor cores via mma.sync): -> g_qkv fp32 [32768,1536]
    gemm_kernel<1><<<dim3(12, MT_TILES), 256, SMEM_GEMM_BYTES>>>(nullptr, nullptr);

    // 3) block-diagonal attention (2 heads/block) -> g_a2 (split bf16)
    attn_kernel<<<BATCH * 4 * 2 * 128, 256>>>();

    // 4) output GEMM + bias: -> out fp32 [32768,512]
    gemm_kernel<2><<<dim3(4, MT_TILES), 256, SMEM_GEMM_BYTES>>>(out, b_out);
}

// round 16
// speedup vs baseline: 1.1082x; 1.0001x over previous
#include <cuda_runtime.h>
#include <cuda_bf16.h>
#include <cstdint>
#include <math.h>

// ---------------------------------------------------------------------------
// Problem constants
// ---------------------------------------------------------------------------
#define BATCH   8
#define NTOK    4096
#define MTOT    32768          // BATCH*NTOK
#define MT_TILES 256           // MTOT/128
#define KCHUNKS 24             // logical K' = 1536 = 24 * 64 ([Ah|Al|Ah]x[Bh|Bh|Bl])
#define ATT_SCALE 0.125f

// ---------------------------------------------------------------------------
// Device scratch. Physical storage holds only UNIQUE chunks:
//   A: 16 chunks (0-7 = Ah, 8-15 = Al); logical kc>=16 re-reads Ah (kc-16).
//   B: 16 chunks (0-7 = Bh, 8-15 = Bl); logical kc in [8,16) re-reads Bh (kc-8),
//      logical kc>=16 reads Bl (kc-8).
// Tile (kc, t): 16KB SW128-swizzled 128x128B block at uint4 idx (kc*NT+t)*1024.
// ---------------------------------------------------------------------------
__device__ float g_qkv[(size_t)MTOT * 1536];                 // fp32 qkv
__device__ uint4 g_a1[(size_t)MTOT * 1024 * 2 / 16];         // x split
__device__ uint4 g_a2[(size_t)MTOT * 1024 * 2 / 16];         // attn out split
__device__ uint4 g_b1[(size_t)1536 * 1024 * 2 / 16];         // w_qkv split
__device__ uint4 g_b2[(size_t)512  * 1024 * 2 / 16];         // w_out split

// ---------------------------------------------------------------------------
// PTX helpers (sm_100 baseline-safe: no tcgen05)
// ---------------------------------------------------------------------------
__device__ __forceinline__ uint32_t smem_u32(const void* p) {
    uint32_t a;
    asm("{ .reg .u64 t; cvta.to.shared.u64 t, %1; cvt.u32.u64 %0, t; }"
        : "=r"(a) : "l"(p));
    return a;
}
__device__ __forceinline__ void mbar_init(uint32_t a, uint32_t n) {
    asm volatile("mbarrier.init.shared.b64 [%0], %1;" :: "r"(a), "r"(n) : "memory");
}
__device__ __forceinline__ void mbar_expect_tx(uint32_t a, uint32_t tx) {
    asm volatile("mbarrier.arrive.expect_tx.shared.b64 _, [%0], %1;"
                 :: "r"(a), "r"(tx) : "memory");
}
__device__ __forceinline__ void mbar_arrive(uint32_t a) {
    asm volatile("mbarrier.arrive.shared.b64 _, [%0];" :: "r"(a) : "memory");
}
__device__ __forceinline__ void mbar_wait(uint32_t a, uint32_t ph) {
    uint32_t done;
    asm volatile("{ .reg .pred p; mbarrier.try_wait.parity.acquire.cta.shared::cta.b64 p, [%1], %2; selp.b32 %0, 1, 0, p; }"
                 : "=r"(done) : "r"(a), "r"(ph) : "memory");
    while (!done) {
        asm volatile("{ .reg .pred p; mbarrier.try_wait.parity.acquire.cta.shared::cta.b64 p, [%1], %2, 0x989680; selp.b32 %0, 1, 0, p; }"
                     : "=r"(done) : "r"(a), "r"(ph) : "memory");
    }
}
__device__ __forceinline__ void bulk_g2s(uint32_t dst, const void* src,
                                         uint32_t bytes, uint32_t mbar) {
    asm volatile("cp.async.bulk.shared::cluster.global.mbarrier::complete_tx::bytes [%0], [%1], %2, [%3];"
                 :: "r"(dst), "l"(src), "r"(bytes), "r"(mbar) : "memory");
}
#define FENCE_ASYNC_SHARED() asm volatile("fence.proxy.async.shared::cta;" ::: "memory")

__device__ __forceinline__ void ldmat_x4(uint32_t& r0, uint32_t& r1,
                                         uint32_t& r2, uint32_t& r3, uint32_t addr) {
    asm volatile("ldmatrix.sync.aligned.m8n8.x4.shared.b16 {%0,%1,%2,%3}, [%4];"
                 : "=r"(r0), "=r"(r1), "=r"(r2), "=r"(r3) : "r"(addr));
}
__device__ __forceinline__ void mma_bf16(float& d0, float& d1, float& d2, float& d3,
                                         uint32_t a0, uint32_t a1, uint32_t a2, uint32_t a3,
                                         uint32_t b0, uint32_t b1) {
    asm volatile("mma.sync.aligned.m16n8k16.row.col.f32.bf16.bf16.f32 "
                 "{%0,%1,%2,%3}, {%4,%5,%6,%7}, {%8,%9}, {%0,%1,%2,%3};"
                 : "+f"(d0), "+f"(d1), "+f"(d2), "+f"(d3)
                 : "r"(a0), "r"(a1), "r"(a2), "r"(a3), "r"(b0), "r"(b1));
}

// ---------------------------------------------------------------------------
// bf16 split helpers
// ---------------------------------------------------------------------------
__device__ __forceinline__ uint32_t pack2(__nv_bfloat16 a, __nv_bfloat16 b) {
    return (uint32_t)__bfloat16_as_ushort(a) | ((uint32_t)__bfloat16_as_ushort(b) << 16);
}
__device__ __forceinline__ void split2(float a, float b, uint32_t& hi, uint32_t& lo) {
    __nv_bfloat16 ha = __float2bfloat16_rn(a), hb = __float2bfloat16_rn(b);
    __nv_bfloat16 la = __float2bfloat16_rn(a - __bfloat162float(ha));
    __nv_bfloat16 lb = __float2bfloat16_rn(b - __bfloat162float(hb));
    hi = pack2(ha, hb); lo = pack2(la, lb);
}
__device__ __forceinline__ uint32_t swz(uint32_t off) {   // SW128 swizzle
    return off ^ ((off >> 3) & 0x70);
}

// Logical chunk -> physical chunk index
__device__ __forceinline__ int a_src(int kc) { return (kc < 16) ? kc : kc - 16; }
__device__ __forceinline__ int b_src(int kc) { return (kc < 8) ? kc : kc - 8; }

// ---------------------------------------------------------------------------
// FUSED conversion kernel: one launch converts x, w_qkv, w_out into their
// chunked/swizzled bf16 hi/lo layouts. Grid partition by blockIdx.x:
//   [0, 8192)          -> x      (32768 rows, MT_TILES=256 row-tiles)
//   [8192, 8192+384)   -> w_qkv  (1536 rows, NT=12)
//   [8576, 8576+128)   -> w_out  (512 rows,  NT=4)
// ---------------------------------------------------------------------------
#define CONV_XB    8192
#define CONV_W1B   384
#define CONV_GRID  (CONV_XB + CONV_W1B + 128)

__global__ __launch_bounds__(256) void conv_all_kernel(
    const float* __restrict__ x, const float* __restrict__ w_qkv,
    const float* __restrict__ w_out)
{
    int blk = blockIdx.x;
    const float* src;
    uint4* dst;
    int tilesN;                 // tiles along the row dimension
    if (blk < CONV_XB)                { src = x;     dst = g_a1; tilesN = MT_TILES; }
    else if (blk < CONV_XB + CONV_W1B){ src = w_qkv; dst = g_b1; tilesN = 12; blk -= CONV_XB; }
    else                              { src = w_out; dst = g_b2; tilesN = 4;  blk -= CONV_XB + CONV_W1B; }

    const int t = blk * 256 + threadIdx.x;
    const int row = t >> 6, c8 = t & 63;
    const int k = c8 << 3;

    const float* rr = src + (size_t)row * 512 + k;
    float4 v0 = *(const float4*)rr, v1 = *(const float4*)(rr + 4);
    uint32_t h[4], l[4];
    split2(v0.x, v0.y, h[0], l[0]); split2(v0.z, v0.w, h[1], l[1]);
    split2(v1.x, v1.y, h[2], l[2]); split2(v1.z, v1.w, h[3], l[3]);

    const int rt = row >> 7, r = row & 127;
    const int kc = k >> 6, c = k & 63;
    const uint32_t u4 = swz((uint32_t)(r * 128 + c * 2)) >> 4;

    dst[((size_t)(kc * tilesN + rt) << 10) + u4]       = make_uint4(h[0], h[1], h[2], h[3]);
    dst[((size_t)((8 + kc) * tilesN + rt) << 10) + u4] = make_uint4(l[0], l[1], l[2], l[3]);
}

// ---------------------------------------------------------------------------
// mma.sync bf16 GEMM: C = Ah*Bh + Al*Bh + Ah*Bl over 24 logical chunks of 64.
// 128x128 CTA tile, 256 threads (8 warps, 2x4 grid, 64x32 warp tile),
// 3-stage cp.async.bulk pipeline with per-warp empty barriers.
// Consumer release = __syncwarp + fence.proxy.async + arrive.
// Rotating producer (warp (kc+3)&7). [Exact R11/R14 configuration.]
// ---------------------------------------------------------------------------
#define SMEM_GEMM_BYTES (1024 + 1024 + 3 * 32768)

template <int WHICH>   // 1: qkv GEMM (C=g_qkv, NT=12), 2: out GEMM (C=out+bias, NT=4)
__global__ __launch_bounds__(256, 2) void gemm_kernel(float* __restrict__ CoutP,
                                                      const float* __restrict__ bias)
{
    constexpr int NT = (WHICH == 1) ? 12 : 4;
    constexpr int NCOLS = NT * 128;
    extern __shared__ __align__(1024) char smem_raw[];
    const uint32_t sb = (smem_u32(smem_raw) + 1023u) & ~1023u;

    const int tid  = threadIdx.x;
    const int wid  = tid >> 5, l = tid & 31;
    const int mt   = blockIdx.y, nt = blockIdx.x;
    const int m0   = (wid >> 2) * 64;      // warp m offset in tile
    const int n0   = (wid & 3)  * 32;      // warp n offset in tile
    const uint32_t xmask = (uint32_t)(l & 7) << 4;

    const char* Abase = (WHICH == 1) ? (const char*)g_a1 : (const char*)g_a2;
    const char* Bbase = (WHICH == 1) ? (const char*)g_b1 : (const char*)g_b2;
    float* C = (WHICH == 1) ? g_qkv : CoutP;

    if (tid == 0) {
        #pragma unroll
        for (int s = 0; s < 3; s++) {
            mbar_init(sb + 8 * s, 1);            // full
            mbar_init(sb + 32 + 8 * s, 8);       // empty: 8 warp arrivals
        }
        FENCE_ASYNC_SHARED();
    }
    __syncthreads();

    if (tid == 0) {
        #pragma unroll
        for (int s = 0; s < 3; s++) {
            mbar_expect_tx(sb + 8 * s, 32768);
            bulk_g2s(sb + 1024 + s * 32768,
                     Abase + ((size_t)(a_src(s) * MT_TILES + mt)) * 16384, 16384, sb + 8 * s);
            bulk_g2s(sb + 1024 + s * 32768 + 16384,
                     Bbase + ((size_t)(b_src(s) * NT + nt)) * 16384, 16384, sb + 8 * s);
        }
    }

    float acc[4][4][4];
    #pragma unroll
    for (int i = 0; i < 4; i++)
        #pragma unroll
        for (int j = 0; j < 4; j++)
            #pragma unroll
            for (int q = 0; q < 4; q++) acc[i][j][q] = 0.f;

    const uint32_t arow = (uint32_t)(m0 + (l & 15)) * 128;
    const uint32_t brow = (uint32_t)(n0 + 8 * ((l >> 4) & 1) + (l & 7)) * 128;
    const uint32_t acol_l = 16u * (uint32_t)(l >> 4);
    const uint32_t bcol_l = 16u * (uint32_t)((l >> 3) & 1);

    #pragma unroll 1
    for (int kc = 0; kc < KCHUNKS; kc++) {
        const int rnd = kc / 3;
        const int s = kc - rnd * 3;
        const uint32_t ph = (uint32_t)(rnd & 1);
        mbar_wait(sb + 8 * s, ph);

        const uint32_t abuf = sb + 1024 + s * 32768;
        const uint32_t bbuf = abuf + 16384;

        #pragma unroll
        for (int ks = 0; ks < 4; ks++) {
            uint32_t a[4][4];
            #pragma unroll
            for (int mi = 0; mi < 4; mi++) {
                const uint32_t addr = abuf + arow + (uint32_t)(mi * 16 * 128)
                                    + ((32u * ks + acol_l) ^ xmask);
                ldmat_x4(a[mi][0], a[mi][1], a[mi][2], a[mi][3], addr);
            }
            uint32_t bfr[2][4];
            #pragma unroll
            for (int jj = 0; jj < 2; jj++) {
                const uint32_t addr = bbuf + brow + (uint32_t)(jj * 16 * 128)
                                    + ((32u * ks + bcol_l) ^ xmask);
                ldmat_x4(bfr[jj][0], bfr[jj][1], bfr[jj][2], bfr[jj][3], addr);
            }
            #pragma unroll
            for (int mi = 0; mi < 4; mi++)
                #pragma unroll
                for (int nj = 0; nj < 4; nj++)
                    mma_bf16(acc[mi][nj][0], acc[mi][nj][1], acc[mi][nj][2], acc[mi][nj][3],
                             a[mi][0], a[mi][1], a[mi][2], a[mi][3],
                             bfr[nj >> 1][(nj & 1) * 2], bfr[nj >> 1][(nj & 1) * 2 + 1]);
        }

        __syncwarp();
        FENCE_ASYNC_SHARED();
        if (l == 0) mbar_arrive(sb + 32 + 8 * s);

        if (kc + 3 < KCHUNKS && wid == ((kc + 3) & 7) && l == 0) {
            mbar_wait(sb + 32 + 8 * s, ph);
            mbar_expect_tx(sb + 8 * s, 32768);
            bulk_g2s(abuf, Abase + ((size_t)(a_src(kc + 3) * MT_TILES + mt)) * 16384,
                     16384, sb + 8 * s);
            bulk_g2s(bbuf, Bbase + ((size_t)(b_src(kc + 3) * NT + nt)) * 16384,
                     16384, sb + 8 * s);
        }
    }

    float2 bv[4];
    if (WHICH == 2) {
        #pragma unroll
        for (int nj = 0; nj < 4; nj++) {
            const int col = nt * 128 + n0 + 8 * nj + 2 * (l & 3);
            bv[nj] = make_float2(__ldg(&bias[col]), __ldg(&bias[col + 1]));
        }
    }
    #pragma unroll
    for (int mi = 0; mi < 4; mi++) {
        #pragma unroll
        for (int half = 0; half < 2; half++) {
            const int row = mt * 128 + m0 + 16 * mi + (l >> 2) + 8 * half;
            float* cr = C + (size_t)row * NCOLS + nt * 128;
            #pragma unroll
            for (int nj = 0; nj < 4; nj++) {
                const int col = n0 + 8 * nj + 2 * (l & 3);
                float v0 = acc[mi][nj][2 * half];
                float v1 = acc[mi][nj][2 * half + 1];
                if (WHICH == 2) { v0 += bv[nj].x; v1 += bv[nj].y; }
                *(float2*)&cr[col] = make_float2(v0, v1);
            }
        }
    }
}

// ---------------------------------------------------------------------------
// Block-diagonal attention v4: two heads per block. PLAIN layouts (identical
// to the validated 606.2us kernel) — the only change vs that version is that
// QK and AV smem reads are float4-vectorized AT THE SAME ADDRESSES with the
// same accumulation order (d ascending, j ascending): bit-identical results,
// 4x fewer LDS instructions (conflict degree unchanged, phase count halved).
// ---------------------------------------------------------------------------
__global__ __launch_bounds__(256) void attn_kernel()
{
    __shared__ float qs[16][132], ks[16][132], vs[16][132];
    __shared__ float ps[2][16][17];

    const int gid = blockIdx.x;            // 0..8191
    const int bj = gid & 127;
    const int bi = (gid >> 7) & 1;
    const int hp = (gid >> 8) & 3;         // head pair
    const int b  = gid >> 10;

    const int tid = threadIdx.x;

    // token index for group row r (r = x*4+y): n = (bi*4+x)*512 + bj*4+y
    #pragma unroll
    for (int t = tid; t < 512; t += 256) {
        const int r = t >> 5, c = (t & 31) * 4;
        const int x = r >> 2, y = r & 3;
        const int n = (bi * 4 + x) * 512 + bj * 4 + y;
        const size_t base = ((size_t)(b * NTOK + n)) * 1536 + hp * 128 + c;
        *(float4*)&qs[r][c] = *(const float4*)(g_qkv + base);
        *(float4*)&ks[r][c] = *(const float4*)(g_qkv + base + 512);
        *(float4*)&vs[r][c] = *(const float4*)(g_qkv + base + 1024);
    }
    __syncthreads();

    // 512 dots (2 heads x 16 x 16); float4 along d, same order as scalar.
    #pragma unroll
    for (int t = tid; t < 512; t += 256) {
        const int hh = t >> 8, i = (t >> 4) & 15, j = t & 15;
        const float4* q4 = (const float4*)&qs[i][hh * 64];   // 16B-aligned (row=528B)
        const float4* k4 = (const float4*)&ks[j][hh * 64];
        float s = 0.f;
        #pragma unroll
        for (int d4 = 0; d4 < 16; d4++) {
            const float4 qa = q4[d4], kb = k4[d4];
            s = fmaf(qa.x, kb.x, s); s = fmaf(qa.y, kb.y, s);
            s = fmaf(qa.z, kb.z, s); s = fmaf(qa.w, kb.w, s);
        }
        ps[hh][i][j] = s * ATT_SCALE;
    }
    __syncthreads();

    // Row softmax: 32 threads (2 heads x 16 rows)
    if (tid < 32) {
        const int hh = tid >> 4, i = tid & 15;
        float mx = ps[hh][i][0];
        #pragma unroll
        for (int j = 1; j < 16; j++) mx = fmaxf(mx, ps[hh][i][j]);
        float sum = 0.f;
        #pragma unroll
        for (int j = 0; j < 16; j++) {
            const float e = __expf(ps[hh][i][j] - mx);
            ps[hh][i][j] = e;
            sum += e;
        }
        const float inv = 1.f / sum;
        #pragma unroll
        for (int j = 0; j < 16; j++) ps[hh][i][j] *= inv;
    }
    __syncthreads();

    // out[i][hh*64 + d]: thread owns (row r, head hh, 8 contiguous d).
    // b0 = hh*64 + d0 is 8-aligned; both float4s are at plain addresses.
    const int r  = tid >> 4;
    const int cc = tid & 15;
    const int hh = cc >> 3;
    const int d0 = (cc & 7) * 8;
    const int b0 = hh * 64 + d0;

    float o[8];
    #pragma unroll
    for (int dd = 0; dd < 8; dd++) o[dd] = 0.f;
    #pragma unroll
    for (int j = 0; j < 16; j++) {
        const float pv = ps[hh][r][j];
        const float4 v0 = *(const float4*)&vs[j][b0];
        const float4 v1 = *(const float4*)&vs[j][b0 + 4];
        o[0] = fmaf(pv, v0.x, o[0]); o[1] = fmaf(pv, v0.y, o[1]);
        o[2] = fmaf(pv, v0.z, o[2]); o[3] = fmaf(pv, v0.w, o[3]);
        o[4] = fmaf(pv, v1.x, o[4]); o[5] = fmaf(pv, v1.y, o[5]);
        o[6] = fmaf(pv, v1.z, o[6]); o[7] = fmaf(pv, v1.w, o[7]);
    }

    uint32_t hhv[4], llv[4];
    split2(o[0], o[1], hhv[0], llv[0]); split2(o[2], o[3], hhv[1], llv[1]);
    split2(o[4], o[5], hhv[2], llv[2]); split2(o[6], o[7], hhv[3], llv[3]);

    const int x = r >> 2, y = r & 3;
    const int n = (bi * 4 + x) * 512 + bj * 4 + y;
    const int m = b * NTOK + n;
    const int mt = m >> 7, rr = m & 127;
    const int h = hp * 2 + hh;
    const uint32_t u4 = swz((uint32_t)(rr * 128 + d0 * 2)) >> 4;

    g_a2[((size_t)(h * MT_TILES + mt) << 10) + u4]       = make_uint4(hhv[0], hhv[1], hhv[2], hhv[3]);
    g_a2[((size_t)((8 + h) * MT_TILES + mt) << 10) + u4] = make_uint4(llv[0], llv[1], llv[2], llv[3]);
}

// ---------------------------------------------------------------------------
extern "C" void kernel_launch(void* const* d_in, const int* in_sizes, int n_in,
                              void* d_out, int out_size)
{
    const float* x     = (const float*)d_in[0];   // [8,4096,512]
    const float* w_qkv = (const float*)d_in[1];   // [1536,512]
    const float* w_out = (const float*)d_in[2];   // [512,512]
    const float* b_out = (const float*)d_in[3];   // [512]
    float* out = (float*)d_out;                   // [8,4096,512]

    cudaFuncSetAttribute(gemm_kernel<1>, cudaFuncAttributeMaxDynamicSharedMemorySize, SMEM_GEMM_BYTES);
    cudaFuncSetAttribute(gemm_kernel<2>, cudaFuncAttributeMaxDynamicSharedMemorySize, SMEM_GEMM_BYTES);

    // 1) fused split/convert of x, w_qkv, w_out (one launch)
    conv_all_kernel<<<CONV_GRID, 256>>>(x, w_qkv, w_out);

    // 2) QKV GEMM (tensor cores via mma.sync): -> g_qkv fp32 [32768,1536]
    gemm_kernel<1><<<dim3(12, MT_TILES), 256, SMEM_GEMM_BYTES>>>(nullptr, nullptr);

    // 3) block-diagonal attention (2 heads/block) -> g_a2 (split bf16)
    attn_kernel<<<BATCH * 4 * 2 * 128, 256>>>();

    // 4) output GEMM + bias: -> out fp32 [32768,512]
    gemm_kernel<2><<<dim3(4, MT_TILES), 256, SMEM_GEMM_BYTES>>>(out, b_out);
}